// round 9
// baseline (speedup 1.0000x reference)
#include <cuda_runtime.h>
#include <cuda_bf16.h>
#include <math.h>

// Shapes (fixed dataset):
//   x_all: [100000, 256] f32, n_id: [50000] i32, edge_index: [2, 300000] i32
//   W_sage: [256,256] f32, b_sage: [256] f32, W_cls: [3,256] f32, b_cls: [3] f32
//   out: [50000, 3] f32 (log_softmax)
//
// out = log_softmax( mean_j( x[j] @ Wc ) + bc )  (linearity)
// 4-kernel PDL pipeline: P0 weight-fusion -> P1 project -> P2 edge REDG -> P3 softmax
#define NMAX 50000
#define FDIM 256
#define F4   64
#define CCLS 3

__device__ float  g_Wc [CCLS * FDIM];
__device__ float  g_bc [CCLS];
__device__ float4 g_z  [NMAX];
__device__ float4 g_acc[NMAX];

__device__ __forceinline__ void pdl_wait()    { asm volatile("griddepcontrol.wait;" ::: "memory"); }
__device__ __forceinline__ void pdl_trigger() { asm volatile("griddepcontrol.launch_dependents;" ::: "memory"); }
__device__ __forceinline__ void redg_v4(float4* p, float4 v) {
    asm volatile("red.global.add.v4.f32 [%0], {%1, %2, %3, %4};"
                 :: "l"(p), "f"(v.x), "f"(v.y), "f"(v.z), "f"(v.w) : "memory");
}

// ---------------------------------------------------------------------------
// Kernel 0: parallel weight fusion. One warp per output element.
// ---------------------------------------------------------------------------
__global__ void k_init(const float* __restrict__ W_sage,
                       const float* __restrict__ b_sage,
                       const float* __restrict__ W_cls,
                       const float* __restrict__ b_cls) {
    int gid  = blockIdx.x * blockDim.x + threadIdx.x;
    int ww   = gid >> 5;
    int lane = gid & 31;
    const unsigned full = 0xffffffffu;

    if (ww < CCLS * FDIM) {
        int c = ww >> 8;
        int k = ww & 255;
        const float4* wrow = reinterpret_cast<const float4*>(W_sage + k * FDIM);
        const float4* crow = reinterpret_cast<const float4*>(W_cls  + c * FDIM);
        float4 a0 = __ldg(&wrow[lane]);      float4 b0 = __ldg(&crow[lane]);
        float4 a1 = __ldg(&wrow[lane + 32]); float4 b1 = __ldg(&crow[lane + 32]);
        float s = fmaf(a0.x, b0.x, fmaf(a0.y, b0.y, fmaf(a0.z, b0.z, a0.w * b0.w)))
                + fmaf(a1.x, b1.x, fmaf(a1.y, b1.y, fmaf(a1.z, b1.z, a1.w * b1.w)));
        #pragma unroll
        for (int off = 16; off > 0; off >>= 1)
            s += __shfl_down_sync(full, s, off);
        if (lane == 0) g_Wc[c * FDIM + k] = s;
    } else if (ww < CCLS * FDIM + CCLS) {
        int c = ww - CCLS * FDIM;
        const float4* brow = reinterpret_cast<const float4*>(b_sage);
        const float4* crow = reinterpret_cast<const float4*>(W_cls + c * FDIM);
        float4 a0 = __ldg(&brow[lane]);      float4 b0 = __ldg(&crow[lane]);
        float4 a1 = __ldg(&brow[lane + 32]); float4 b1 = __ldg(&crow[lane + 32]);
        float s = fmaf(a0.x, b0.x, fmaf(a0.y, b0.y, fmaf(a0.z, b0.z, a0.w * b0.w)))
                + fmaf(a1.x, b1.x, fmaf(a1.y, b1.y, fmaf(a1.z, b1.z, a1.w * b1.w)));
        #pragma unroll
        for (int off = 16; off > 0; off >>= 1)
            s += __shfl_down_sync(full, s, off);
        if (lane == 0) g_bc[c] = s + __ldg(&b_cls[c]);
    }
    pdl_trigger();
}

// ---------------------------------------------------------------------------
// Kernel 1: project. One warp per node: z[i] = x_all[n_id[i]] @ Wc, .w = 1.
// Row fetch is pre-wait prologue (depends only on inputs, not g_Wc).
// ---------------------------------------------------------------------------
__global__ void k_z(const float4* __restrict__ x_all4,
                    const int* __restrict__ n_id, int N) {
    __shared__ float sW[CCLS][FDIM];
    int t    = threadIdx.x;
    int w    = (blockIdx.x * blockDim.x + t) >> 5;
    int lane = t & 31;

    float4 a0 = make_float4(0.f, 0.f, 0.f, 0.f), a1 = a0;
    if (w < N) {
        int row = __ldg(&n_id[w]);
        const float4* xp = x_all4 + (long long)row * F4;
        a0 = __ldg(&xp[lane]);
        a1 = __ldg(&xp[lane + 32]);
    }

    pdl_wait();   // g_Wc ready
    for (int idx = t; idx < CCLS * FDIM; idx += blockDim.x)
        sW[idx >> 8][idx & 255] = g_Wc[idx];
    __syncthreads();

    if (w < N) {
        int k0 = lane * 4, k1 = (lane + 32) * 4;
        float s0, s1, s2;
        {
            float t0, t1, t2;
            t0 = fmaf(a0.x, sW[0][k0], fmaf(a0.y, sW[0][k0+1], fmaf(a0.z, sW[0][k0+2], a0.w * sW[0][k0+3])));
            t1 = fmaf(a0.x, sW[1][k0], fmaf(a0.y, sW[1][k0+1], fmaf(a0.z, sW[1][k0+2], a0.w * sW[1][k0+3])));
            t2 = fmaf(a0.x, sW[2][k0], fmaf(a0.y, sW[2][k0+1], fmaf(a0.z, sW[2][k0+2], a0.w * sW[2][k0+3])));
            s0 = fmaf(a1.x, sW[0][k1], fmaf(a1.y, sW[0][k1+1], fmaf(a1.z, sW[0][k1+2], fmaf(a1.w, sW[0][k1+3], t0))));
            s1 = fmaf(a1.x, sW[1][k1], fmaf(a1.y, sW[1][k1+1], fmaf(a1.z, sW[1][k1+2], fmaf(a1.w, sW[1][k1+3], t1))));
            s2 = fmaf(a1.x, sW[2][k1], fmaf(a1.y, sW[2][k1+1], fmaf(a1.z, sW[2][k1+2], fmaf(a1.w, sW[2][k1+3], t2))));
        }
        const unsigned full = 0xffffffffu;
        #pragma unroll
        for (int off = 16; off > 0; off >>= 1) {
            s0 += __shfl_down_sync(full, s0, off);
            s1 += __shfl_down_sync(full, s1, off);
            s2 += __shfl_down_sync(full, s2, off);
        }
        if (lane == 0) {
            float4 zv = make_float4(s0, s1, s2, 1.0f);
            g_z[w]   = zv;
            g_acc[w] = zv;   // self loop (+count)
        }
    }
    pdl_trigger();
}

// ---------------------------------------------------------------------------
// Kernel 2: edge aggregation. FOUR edges per thread (int4 index loads,
// 4 independent z reads + 4 REDG v4 in flight). E=300000 % 4 == 0; generic
// scalar tail anyway.
// ---------------------------------------------------------------------------
__global__ void k_edge(const int* __restrict__ src,
                       const int* __restrict__ dst, int E) {
    int q  = blockIdx.x * blockDim.x + threadIdx.x;   // quad index
    int e0 = q * 4;
    if (e0 >= E) { pdl_wait(); pdl_trigger(); return; }

    if (e0 + 3 < E) {
        int4 sv = __ldg(reinterpret_cast<const int4*>(src) + q);
        int4 dv = __ldg(reinterpret_cast<const int4*>(dst) + q);
        pdl_wait();   // g_z / g_acc ready
        float4 v0 = __ldg(&g_z[sv.x]);
        float4 v1 = __ldg(&g_z[sv.y]);
        float4 v2 = __ldg(&g_z[sv.z]);
        float4 v3 = __ldg(&g_z[sv.w]);
        redg_v4(&g_acc[dv.x], v0);
        redg_v4(&g_acc[dv.y], v1);
        redg_v4(&g_acc[dv.z], v2);
        redg_v4(&g_acc[dv.w], v3);
    } else {
        pdl_wait();
        for (int e = e0; e < E; e++) {
            int s = __ldg(&src[e]);
            int d = __ldg(&dst[e]);
            redg_v4(&g_acc[d], __ldg(&g_z[s]));
        }
    }
    pdl_trigger();
}

// ---------------------------------------------------------------------------
// Kernel 3: finalize. TWO nodes per thread -> two independent latency chains
// per thread (kernel is latency-bound at ~2.6 warps/SMSP). block=128 keeps
// the same grid spread across SMs.
// ---------------------------------------------------------------------------
__global__ void k_final(float* __restrict__ out, int N) {
    int p  = blockIdx.x * blockDim.x + threadIdx.x;
    int i0 = p * 2;
    pdl_wait();   // all REDG from k_edge visible
    if (i0 >= N) return;
    int i1 = i0 + 1;
    bool has1 = (i1 < N);

    float4 a = g_acc[i0];
    float4 b = has1 ? g_acc[i1] : make_float4(0.f, 0.f, 0.f, 1.f);
    float bc0 = g_bc[0], bc1 = g_bc[1], bc2 = g_bc[2];

    float inva = __frcp_rn(a.w);
    float invb = __frcp_rn(b.w);
    float as0 = fmaf(a.x, inva, bc0), bs0 = fmaf(b.x, invb, bc0);
    float as1 = fmaf(a.y, inva, bc1), bs1 = fmaf(b.y, invb, bc1);
    float as2 = fmaf(a.z, inva, bc2), bs2 = fmaf(b.z, invb, bc2);

    float am = fmaxf(as0, fmaxf(as1, as2));
    float bm = fmaxf(bs0, fmaxf(bs1, bs2));
    float ae0 = __expf(as0 - am), be0 = __expf(bs0 - bm);
    float ae1 = __expf(as1 - am), be1 = __expf(bs1 - bm);
    float ae2 = __expf(as2 - am), be2 = __expf(bs2 - bm);
    float alse = am + __logf(ae0 + ae1 + ae2);
    float blse = bm + __logf(be0 + be1 + be2);

    out[i0 * 3 + 0] = as0 - alse;
    out[i0 * 3 + 1] = as1 - alse;
    out[i0 * 3 + 2] = as2 - alse;
    if (has1) {
        out[i1 * 3 + 0] = bs0 - blse;
        out[i1 * 3 + 1] = bs1 - blse;
        out[i1 * 3 + 2] = bs2 - blse;
    }
}

// ---------------------------------------------------------------------------
static inline void launch_pdl(void* fn, dim3 grid, dim3 block,
                              void** args, bool pdl_in) {
    cudaLaunchConfig_t cfg = {};
    cfg.gridDim  = grid;
    cfg.blockDim = block;
    cfg.dynamicSmemBytes = 0;
    cfg.stream = 0;
    cudaLaunchAttribute attr[1];
    int nattr = 0;
    if (pdl_in) {
        attr[0].id = cudaLaunchAttributeProgrammaticStreamSerialization;
        attr[0].val.programmaticStreamSerializationAllowed = 1;
        nattr = 1;
    }
    cfg.attrs = attr;
    cfg.numAttrs = nattr;
    cudaLaunchKernelExC(&cfg, fn, args);
}

extern "C" void kernel_launch(void* const* d_in, const int* in_sizes, int n_in,
                              void* d_out, int out_size) {
    const float* x_all  = (const float*)d_in[0];
    const int*   n_id   = (const int*)  d_in[1];
    const int*   eidx   = (const int*)  d_in[2];
    const float* W_sage = (const float*)d_in[3];
    const float* b_sage = (const float*)d_in[4];
    const float* W_cls  = (const float*)d_in[5];
    const float* b_cls  = (const float*)d_in[6];
    float* out = (float*)d_out;

    int N = in_sizes[1];          // 50000
    int E = in_sizes[2] / 2;      // 300000
    const int* src = eidx;        // edge_index[0, :]
    const int* dst = eidx + E;    // edge_index[1, :]

    // k_init: 771 warp-tasks
    {
        int threads = (CCLS * FDIM + CCLS) * 32;
        dim3 g((threads + 255) / 256), b(256);
        void* args[] = {(void*)&W_sage, (void*)&b_sage, (void*)&W_cls, (void*)&b_cls};
        launch_pdl((void*)k_init, g, b, args, false);
    }
    // k_z: one warp per node
    {
        const float4* x4 = reinterpret_cast<const float4*>(x_all);
        long long th = (long long)N * 32;
        dim3 g((unsigned)((th + 255) / 256)), b(256);
        void* args[] = {(void*)&x4, (void*)&n_id, (void*)&N};
        launch_pdl((void*)k_z, g, b, args, true);
    }
    // k_edge: four edges per thread
    {
        int quads = (E + 3) / 4;
        dim3 g((quads + 255) / 256), b(256);
        void* args[] = {(void*)&src, (void*)&dst, (void*)&E};
        launch_pdl((void*)k_edge, g, b, args, true);
    }
    // k_final: two nodes per thread, block=128 (same grid spread)
    {
        int pairs = (N + 1) / 2;
        dim3 g((pairs + 127) / 128), b(128);
        void* args[] = {(void*)&out, (void*)&N};
        launch_pdl((void*)k_final, g, b, args, true);
    }
}